// round 7
// baseline (speedup 1.0000x reference)
#include <cuda_runtime.h>
#include <cstdint>

// YoloLayer: x (B, 3*12, G, G) f32 -> out (B, 3*G*G, 12) f32
// 1 point/thread; warp-private smem staging; grid (91, 3, B).
// Sigmoid via single-MUFU tanh.approx: sig(x) = 0.5*tanh(0.5x) + 0.5.

#define G_  152
#define GG_ (G_ * G_)        // 23104 (divisible by 32)
#define NA_ 3
#define NATTR 12
#define EXP_CLAMP_ 1000.0f
#define BLK 256

__device__ __forceinline__ float sigmoidf_(float v) {
    float t;
    asm("tanh.approx.f32 %0, %1;" : "=f"(t) : "f"(v * 0.5f));
    return fmaf(t, 0.5f, 0.5f);
}

__global__ __launch_bounds__(BLK)
void yolo_kernel(const float* __restrict__ x,
                 const float* __restrict__ anchors,
                 const int*   __restrict__ img_size_p,
                 float* __restrict__ out)
{
    __shared__ float sbuf[BLK * NATTR];          // 12 KB; 1536 B per warp

    const int tid  = threadIdx.x;
    const int lane = tid & 31;
    const int a    = blockIdx.y;                 // anchor index directly
    const int ba   = blockIdx.z * NA_ + a;       // b*3 + a
    const int s    = blockIdx.x * BLK + tid;     // spatial point
    const int warpStart = blockIdx.x * BLK + (tid & ~31);

    if (warpStart >= GG_) return;                // whole warp out (GG_ % 32 == 0)

    // img_size may arrive as int32 or float32 bits.
    int ibits = img_size_p[0];
    float img = (ibits >= 1 && ibits <= (1 << 20)) ? (float)ibits : __int_as_float(ibits);
    const float stride = img / (float)G_;

    int gy = s / G_;                             // constant div -> mul/shift
    int gx = s - gy * G_;

    const float an0 = anchors[a * 5 + 0];
    const float an1 = anchors[a * 5 + 1];
    const float an2 = anchors[a * 5 + 2];

    // 12 channel-strided scalar loads; lanes consecutive in s -> full 128B lines.
    const float* base = x + (size_t)ba * NATTR * GG_ + s;
    float p[NATTR];
#pragma unroll
    for (int attr = 0; attr < NATTR; ++attr)
        p[attr] = __ldcs(base + attr * GG_);

    float c0 = (sigmoidf_(p[0]) + (float)gx) * stride;
    float c1 = (sigmoidf_(p[1]) + (float)gy) * stride;
    float c2 =  sigmoidf_(p[2]);
    float c3 = fminf(__expf(p[3]), EXP_CLAMP_) * an0;   // (anchor/stride)*stride cancels
    float c4 = fminf(__expf(p[4]), EXP_CLAMP_) * an1;
    float c5 = fminf(__expf(p[5]), EXP_CLAMP_) * an2;

    // Stage this warp's 32 points (1536 B) in its own smem slice.
    float4* sv = reinterpret_cast<float4*>(sbuf + tid * NATTR);
    sv[0] = make_float4(c0, c1, c2, c3);
    sv[1] = make_float4(c4, c5, p[6], p[7]);
    sv[2] = make_float4(sigmoidf_(p[8]),  sigmoidf_(p[9]),
                        sigmoidf_(p[10]), sigmoidf_(p[11]));
    __syncwarp();

    // Warp streams its 1536 B out as 3 coalesced float4 wavefront sets.
    const float4* wbuf = reinterpret_cast<const float4*>(sbuf + (tid & ~31) * NATTR);
    float4* obase = reinterpret_cast<float4*>(out) + ((size_t)ba * GG_ + warpStart) * 3;
    __stcs(obase + lane,      wbuf[lane]);
    __stcs(obase + lane + 32, wbuf[lane + 32]);
    __stcs(obase + lane + 64, wbuf[lane + 64]);
}

extern "C" void kernel_launch(void* const* d_in, const int* in_sizes, int n_in,
                              void* d_out, int out_size)
{
    const float* x        = (const float*)d_in[0];
    const float* anchors  = (const float*)d_in[1];
    const int*   img_size = (const int*)d_in[2];
    float* out = (float*)d_out;

    int B = in_sizes[0] / (NA_ * NATTR * GG_);

    dim3 grid((GG_ + BLK - 1) / BLK, NA_, B);    // (91, 3, B)
    yolo_kernel<<<grid, BLK>>>(x, anchors, img_size, out);
}

// round 8
// speedup vs baseline: 1.0113x; 1.0113x over previous
#include <cuda_runtime.h>
#include <cstdint>

// YoloLayer: x (B, 3*12, G, G) f32 -> out (B, 3*G*G, 12) f32
// 2 points/thread via float2 loads (halves LDG issue + DRAM request count).
// Two-phase warp-private smem staging (12 KB total, __syncwarp only):
//   phase A: lanes 0-15 stage their 2 points (= warp's first 32 points), warp stores 1536B
//   phase B: lanes 16-31 stage, warp stores next 1536B
// Grid (46, 3, B). Sigmoid = single-MUFU tanh.approx.

#define G_  152
#define GG_ (G_ * G_)        // 23104
#define NA_ 3
#define NATTR 12
#define EXP_CLAMP_ 1000.0f
#define BLK 256
#define PTS_BLK (BLK * 2)    // 512 points per block

__device__ __forceinline__ float sigmoidf_(float v) {
    float t;
    asm("tanh.approx.f32 %0, %1;" : "=f"(t) : "f"(v * 0.5f));
    return fmaf(t, 0.5f, 0.5f);
}

__global__ __launch_bounds__(BLK, 6)
void yolo_kernel(const float* __restrict__ x,
                 const float* __restrict__ anchors,
                 const int*   __restrict__ img_size_p,
                 float* __restrict__ out)
{
    __shared__ float sbuf[BLK * NATTR];              // 12 KB; 1536 B per warp

    const int tid  = threadIdx.x;
    const int lane = tid & 31;
    const int a    = blockIdx.y;
    const int ba   = blockIdx.z * NA_ + a;           // b*3 + a

    // warp covers 64 contiguous points
    const int warpBase = (blockIdx.x * BLK + (tid & ~31)) * 2;
    if (warpBase >= GG_) return;                     // whole-warp exit (tail exact: 23104-23040=64)

    const int s = warpBase + lane * 2;               // this thread's point pair (s, s+1)

    // img_size may arrive as int32 or float32 bits.
    int ibits = img_size_p[0];
    float img = (ibits >= 1 && ibits <= (1 << 20)) ? (float)ibits : __int_as_float(ibits);
    const float stride = img / (float)G_;

    int gy = s / G_;                                 // s even -> pair never wraps a row
    int gx = s - gy * G_;

    const float an0 = anchors[a * 5 + 0];
    const float an1 = anchors[a * 5 + 1];
    const float an2 = anchors[a * 5 + 2];

    // 12 channel-strided float2 loads (8B aligned); warp reads 256B per load.
    const float* base = x + (size_t)ba * NATTR * GG_ + s;
    float2 p[NATTR];
#pragma unroll
    for (int attr = 0; attr < NATTR; ++attr)
        p[attr] = __ldcs(reinterpret_cast<const float2*>(base + attr * GG_));

    // Compute both points' 12 outputs into registers.
    float4 r0, r1, r2, r3, r4, r5;
    {
        float c0 = (sigmoidf_(p[0].x) + (float)gx) * stride;
        float c1 = (sigmoidf_(p[1].x) + (float)gy) * stride;
        r0 = make_float4(c0, c1, sigmoidf_(p[2].x),
                         fminf(__expf(p[3].x), EXP_CLAMP_) * an0);
        r1 = make_float4(fminf(__expf(p[4].x), EXP_CLAMP_) * an1,
                         fminf(__expf(p[5].x), EXP_CLAMP_) * an2,
                         p[6].x, p[7].x);
        r2 = make_float4(sigmoidf_(p[8].x),  sigmoidf_(p[9].x),
                         sigmoidf_(p[10].x), sigmoidf_(p[11].x));
    }
    {
        float c0 = (sigmoidf_(p[0].y) + (float)(gx + 1)) * stride;
        float c1 = (sigmoidf_(p[1].y) + (float)gy) * stride;
        r3 = make_float4(c0, c1, sigmoidf_(p[2].y),
                         fminf(__expf(p[3].y), EXP_CLAMP_) * an0);
        r4 = make_float4(fminf(__expf(p[4].y), EXP_CLAMP_) * an1,
                         fminf(__expf(p[5].y), EXP_CLAMP_) * an2,
                         p[6].y, p[7].y);
        r5 = make_float4(sigmoidf_(p[8].y),  sigmoidf_(p[9].y),
                         sigmoidf_(p[10].y), sigmoidf_(p[11].y));
    }

    float4* wslice = reinterpret_cast<float4*>(sbuf + (tid & ~31) * NATTR); // 96 float4s
    float4* obase  = reinterpret_cast<float4*>(out) + ((size_t)ba * GG_ + warpBase) * 3;

    // Phase A: lanes 0-15 hold the warp's first 32 points; stage + coalesced store.
    if (lane < 16) {
        float4* sv = wslice + lane * 6;
        sv[0] = r0; sv[1] = r1; sv[2] = r2;
        sv[3] = r3; sv[4] = r4; sv[5] = r5;
    }
    __syncwarp();
    __stcs(obase + lane,      wslice[lane]);
    __stcs(obase + lane + 32, wslice[lane + 32]);
    __stcs(obase + lane + 64, wslice[lane + 64]);
    __syncwarp();

    // Phase B: lanes 16-31 hold the second 32 points.
    if (lane >= 16) {
        float4* sv = wslice + (lane - 16) * 6;
        sv[0] = r0; sv[1] = r1; sv[2] = r2;
        sv[3] = r3; sv[4] = r4; sv[5] = r5;
    }
    __syncwarp();
    __stcs(obase + 96 + lane,      wslice[lane]);
    __stcs(obase + 96 + lane + 32, wslice[lane + 32]);
    __stcs(obase + 96 + lane + 64, wslice[lane + 64]);
}

extern "C" void kernel_launch(void* const* d_in, const int* in_sizes, int n_in,
                              void* d_out, int out_size)
{
    const float* x        = (const float*)d_in[0];
    const float* anchors  = (const float*)d_in[1];
    const int*   img_size = (const int*)d_in[2];
    float* out = (float*)d_out;

    int B = in_sizes[0] / (NA_ * NATTR * GG_);

    dim3 grid((GG_ + PTS_BLK - 1) / PTS_BLK, NA_, B);   // (46, 3, B)
    yolo_kernel<<<grid, BLK>>>(x, anchors, img_size, out);
}